// round 1
// baseline (speedup 1.0000x reference)
#include <cuda_runtime.h>
#include <cstddef>

// Problem constants
#define B_  1024
#define T_  85
#define F_  36
#define H_  512
#define C_  69

// Scratch activations (max 1024 x 2048 fp32)
__device__ float g_bufA[B_ * 4 * H_];
__device__ float g_bufB[B_ * 4 * H_];
__device__ float g_feat[B_ * (2 * F_ + C_)];   // 1024 x 141

// ---------------------------------------------------------------------------
// Tiled SGEMM: C[row, col] = act( sum_k A[row,k] * W[k,col] + bias[col] )
// A: M x K row-major, W: K x N row-major, C written with row stride ldc.
// BM=BN=64, BK=16, 256 threads, 4x4 microtile per thread.
// ---------------------------------------------------------------------------
#define BM 64
#define BN 64
#define BK 16
#define TM 4
#define TN 4

__global__ __launch_bounds__(256)
void gemm_bias_act_kernel(const float* __restrict__ A,
                          const float* __restrict__ W,
                          const float* __restrict__ bias,
                          float* __restrict__ Cout,
                          int M, int N, int K, int ldc, int do_relu)
{
    __shared__ float As[BK][BM];
    __shared__ float Ws[BK][BN + 4];

    const int bm = blockIdx.y * BM;
    const int bn = blockIdx.x * BN;
    const int tid = threadIdx.x;         // 0..255
    const int tr = tid >> 4;             // 0..15 (row group)
    const int tc = tid & 15;             // 0..15 (col group)

    float acc[TM][TN];
#pragma unroll
    for (int i = 0; i < TM; i++)
#pragma unroll
        for (int j = 0; j < TN; j++) acc[i][j] = 0.f;

    for (int k0 = 0; k0 < K; k0 += BK) {
        // Load A tile (BM x BK), store transposed As[k][m]
#pragma unroll
        for (int i = 0; i < 4; i++) {
            int idx = tid * 4 + i;           // 0..1023
            int r = idx / BK;                // 0..63
            int c = idx % BK;                // 0..15
            int gr = bm + r, gc = k0 + c;
            float v = 0.f;
            if (gr < M && gc < K) v = A[(size_t)gr * K + gc];
            As[c][r] = v;
        }
        // Load W tile (BK x BN)
#pragma unroll
        for (int i = 0; i < 4; i++) {
            int idx = tid * 4 + i;
            int r = idx / BN;                // 0..15
            int c = idx % BN;                // 0..63
            int gr = k0 + r, gc = bn + c;
            float v = 0.f;
            if (gr < K && gc < N) v = W[(size_t)gr * N + gc];
            Ws[r][c] = v;
        }
        __syncthreads();

#pragma unroll
        for (int k = 0; k < BK; k++) {
            float a[TM], w[TN];
#pragma unroll
            for (int i = 0; i < TM; i++) a[i] = As[k][tr * TM + i];
#pragma unroll
            for (int j = 0; j < TN; j++) w[j] = Ws[k][tc * TN + j];
#pragma unroll
            for (int i = 0; i < TM; i++)
#pragma unroll
                for (int j = 0; j < TN; j++)
                    acc[i][j] = fmaf(a[i], w[j], acc[i][j]);
        }
        __syncthreads();
    }

    // Epilogue: bias + optional relu, strided store
#pragma unroll
    for (int i = 0; i < TM; i++) {
        int row = bm + tr * TM + i;
        if (row >= M) continue;
#pragma unroll
        for (int j = 0; j < TN; j++) {
            int col = bn + tc * TN + j;
            if (col >= N) continue;
            float v = acc[i][j] + bias[col];
            if (do_relu) v = fmaxf(v, 0.f);
            Cout[(size_t)row * ldc + col] = v;
        }
    }
}

// ---------------------------------------------------------------------------
// Build feat[b, :] = [source[b, t-1, :], source[b, t, :], out[b, t-1, :]]
// ---------------------------------------------------------------------------
__global__ void concat_feat_kernel(const float* __restrict__ src,
                                   const float* __restrict__ out,
                                   float* __restrict__ feat, int t)
{
    const int FEAT = 2 * F_ + C_;   // 141
    int i = blockIdx.x * blockDim.x + threadIdx.x;
    if (i >= B_ * FEAT) return;
    int b = i / FEAT;
    int j = i - b * FEAT;
    float v;
    if (j < F_)
        v = src[(size_t)b * T_ * F_ + (size_t)(t - 1) * F_ + j];
    else if (j < 2 * F_)
        v = src[(size_t)b * T_ * F_ + (size_t)t * F_ + (j - F_)];
    else
        v = out[(size_t)b * T_ * C_ + (size_t)(t - 1) * C_ + (j - 2 * F_)];
    feat[i] = v;
}

// Copy init (= result[:, 0, :]) to the tail of d_out if the harness expects
// the second tuple output as well.
__global__ void copy_init_tail_kernel(float* __restrict__ out)
{
    int i = blockIdx.x * blockDim.x + threadIdx.x;
    if (i >= B_ * C_) return;
    int b = i / C_;
    int c = i - b * C_;
    out[(size_t)B_ * T_ * C_ + i] = out[(size_t)b * T_ * C_ + c];
}

// ---------------------------------------------------------------------------
static inline void gemm(const float* A, const float* W, const float* bias,
                        float* C, int M, int N, int K, int ldc, bool relu)
{
    dim3 grid((N + BN - 1) / BN, (M + BM - 1) / BM);
    gemm_bias_act_kernel<<<grid, 256>>>(A, W, bias, C, M, N, K, ldc, relu ? 1 : 0);
}

extern "C" void kernel_launch(void* const* d_in, const int* in_sizes, int n_in,
                              void* d_out, int out_size)
{
    const float* src  = (const float*)d_in[0];
    const float* wi1  = (const float*)d_in[1];
    const float* bi1  = (const float*)d_in[2];
    const float* wi2  = (const float*)d_in[3];
    const float* bi2  = (const float*)d_in[4];
    const float* wi25 = (const float*)d_in[5];
    const float* bi25 = (const float*)d_in[6];
    const float* wi3  = (const float*)d_in[7];
    const float* bi3  = (const float*)d_in[8];
    const float* w1   = (const float*)d_in[9];
    const float* b1   = (const float*)d_in[10];
    const float* w12  = (const float*)d_in[11];
    const float* b12  = (const float*)d_in[12];
    const float* w2   = (const float*)d_in[13];
    const float* b2   = (const float*)d_in[14];
    const float* w22  = (const float*)d_in[15];
    const float* b22  = (const float*)d_in[16];
    const float* w3   = (const float*)d_in[17];
    const float* b3   = (const float*)d_in[18];
    const float* w4   = (const float*)d_in[19];
    const float* b4   = (const float*)d_in[20];
    const float* w4d  = (const float*)d_in[21];
    const float* b4d  = (const float*)d_in[22];

    float* out = (float*)d_out;

    float* bufA = nullptr;
    float* bufB = nullptr;
    float* feat = nullptr;
    cudaGetSymbolAddress((void**)&bufA, g_bufA);
    cudaGetSymbolAddress((void**)&bufB, g_bufB);
    cudaGetSymbolAddress((void**)&feat, g_feat);

    const int FEAT = 2 * F_ + C_;   // 141
    const int LDO  = T_ * C_;       // output row stride (per batch)

    // ---- getInitialPos: (B, T*F) -> 2048 -> 1024 -> 512 -> 69
    gemm(src,  wi1,  bi1,  bufA, B_, 4 * H_, T_ * F_, 4 * H_, true);
    gemm(bufA, wi2,  bi2,  bufB, B_, 2 * H_, 4 * H_, 2 * H_, true);
    gemm(bufB, wi25, bi25, bufA, B_, H_,     2 * H_, H_,     false);
    gemm(bufA, wi3,  bi3,  out,  B_, C_,     H_,     LDO,    false);   // result[:, 0, :]

    // ---- scan: 84 sequential steps of the 7-layer "follow" MLP
    for (int t = 1; t < T_; t++) {
        concat_feat_kernel<<<(B_ * FEAT + 255) / 256, 256>>>(src, out, feat, t);
        gemm(feat, w1,  b1,  bufA, B_, 4 * H_, FEAT,   4 * H_, true);
        gemm(bufA, w12, b12, bufB, B_, 4 * H_, 4 * H_, 4 * H_, true);
        gemm(bufB, w2,  b2,  bufA, B_, 2 * H_, 4 * H_, 2 * H_, true);
        gemm(bufA, w22, b22, bufB, B_, 2 * H_, 2 * H_, 2 * H_, true);
        gemm(bufB, w3,  b3,  bufA, B_, H_,     2 * H_, H_,     true);
        gemm(bufA, w4,  b4,  bufB, B_, H_,     H_,     H_,     false);
        gemm(bufB, w4d, b4d, out + (size_t)t * C_, B_, C_, H_, LDO, false);
    }

    // ---- second tuple output (init), if present in d_out
    if (out_size >= B_ * T_ * C_ + B_ * C_) {
        copy_init_tail_kernel<<<(B_ * C_ + 255) / 256, 256>>>(out);
    }
}

// round 2
// speedup vs baseline: 1.4365x; 1.4365x over previous
#include <cuda_runtime.h>
#include <cstdint>
#include <cstddef>

// Problem constants
#define B_  1024
#define T_  85
#define F_  36
#define H_  512
#define C_  69

// Scratch activations (max 1024 x 2048 fp32)
__device__ float g_bufA[B_ * 4 * H_];
__device__ float g_bufB[B_ * 4 * H_];

// ---------------------------------------------------------------------------
// TF32 tensor-core GEMM: C = act(A @ W + bias)
// A: M x K row-major (fp32), W: K x N row-major (fp32), C row stride ldc.
// Block tile 128x128x16, 256 threads (8 warps), warp tile 64x32 via
// mma.sync.m16n8k8.tf32 (4 m-tiles x 4 n-tiles per warp).
// mode==1: A is gathered as concat(src[:,t-1,:], src[:,t,:], out[:,t-1,:C]).
// ---------------------------------------------------------------------------
#define BM 128
#define BN 128
#define BK 16

__device__ __forceinline__ uint32_t f2tf32(float x) {
    uint32_t r;
    asm("cvt.rna.tf32.f32 %0, %1;" : "=r"(r) : "f"(x));
    return r;
}

__device__ __forceinline__ void mma_tf32(float (&d)[4],
                                         const uint32_t (&a)[4],
                                         const uint32_t (&b)[2]) {
    asm volatile(
        "mma.sync.aligned.m16n8k8.row.col.f32.tf32.tf32.f32 "
        "{%0,%1,%2,%3}, {%4,%5,%6,%7}, {%8,%9}, {%0,%1,%2,%3};"
        : "+f"(d[0]), "+f"(d[1]), "+f"(d[2]), "+f"(d[3])
        : "r"(a[0]), "r"(a[1]), "r"(a[2]), "r"(a[3]),
          "r"(b[0]), "r"(b[1]));
}

__global__ __launch_bounds__(256, 2)
void gemm_tf32_kernel(const float* __restrict__ A,
                      const float* __restrict__ W,
                      const float* __restrict__ bias,
                      float* __restrict__ Cout,
                      int M, int N, int K, int ldc, int do_relu,
                      int mode,
                      const float* __restrict__ src,
                      const float* __restrict__ prevOut,
                      int t)
{
    __shared__ uint32_t As[BM][20];        // pad 20 -> conflict-free frag loads
    __shared__ uint32_t Bs[BK][BN + 8];    // pad 136 -> conflict-free frag loads

    const int bm  = blockIdx.y * BM;
    const int bn  = blockIdx.x * BN;
    const int tid = threadIdx.x;
    const int lane = tid & 31;
    const int wid  = tid >> 5;       // 0..7
    const int warpM = wid >> 2;      // 0..1 -> 64 rows each
    const int warpN = wid & 3;       // 0..3 -> 32 cols each
    const int gp = lane >> 2;        // 0..7
    const int lq = lane & 3;         // 0..3

    float acc[4][4][4];
#pragma unroll
    for (int i = 0; i < 4; i++)
#pragma unroll
        for (int j = 0; j < 4; j++)
#pragma unroll
            for (int v = 0; v < 4; v++) acc[i][j][v] = 0.f;

    for (int k0 = 0; k0 < K; k0 += BK) {
        // ---- load A tile (BM x BK) ----
#pragma unroll
        for (int i = 0; i < 8; i++) {
            int f   = i * 256 + tid;       // 0..2047
            int row = f >> 4;              // 0..127
            int kc  = f & 15;
            int gk  = k0 + kc;
            float v = 0.f;
            int gr = bm + row;
            if (gk < K) {
                if (mode == 0) {
                    v = A[(size_t)gr * K + gk];
                } else {
                    // gathered concat: [src[b,t-1,:F], src[b,t,:F], out[b,t-1,:C]]
                    if (gk < F_)
                        v = src[(size_t)gr * T_ * F_ + (size_t)(t - 1) * F_ + gk];
                    else if (gk < 2 * F_)
                        v = src[(size_t)gr * T_ * F_ + (size_t)t * F_ + (gk - F_)];
                    else
                        v = prevOut[(size_t)gr * T_ * C_ + (size_t)(t - 1) * C_ + (gk - 2 * F_)];
                }
            }
            As[row][kc] = f2tf32(v);
        }
        // ---- load B tile (BK x BN) ----
#pragma unroll
        for (int i = 0; i < 8; i++) {
            int f   = i * 256 + tid;       // 0..2047
            int row = f >> 7;              // 0..15
            int col = f & 127;
            int gk = k0 + row, gc = bn + col;
            float v = 0.f;
            if (gk < K && gc < N) v = W[(size_t)gk * N + gc];
            Bs[row][col] = f2tf32(v);
        }
        __syncthreads();

        // ---- compute: two k-chunks of 8 ----
#pragma unroll
        for (int kk = 0; kk < BK; kk += 8) {
            uint32_t af[4][4];
            uint32_t bf[4][2];
#pragma unroll
            for (int mt = 0; mt < 4; mt++) {
                int r0 = warpM * 64 + mt * 16 + gp;
                af[mt][0] = As[r0][kk + lq];
                af[mt][1] = As[r0 + 8][kk + lq];
                af[mt][2] = As[r0][kk + lq + 4];
                af[mt][3] = As[r0 + 8][kk + lq + 4];
            }
#pragma unroll
            for (int nt = 0; nt < 4; nt++) {
                int c0 = warpN * 32 + nt * 8 + gp;
                bf[nt][0] = Bs[kk + lq][c0];
                bf[nt][1] = Bs[kk + lq + 4][c0];
            }
#pragma unroll
            for (int mt = 0; mt < 4; mt++)
#pragma unroll
                for (int nt = 0; nt < 4; nt++)
                    mma_tf32(acc[mt][nt], af[mt], bf[nt]);
        }
        __syncthreads();
    }

    // ---- epilogue: bias + relu, strided store ----
#pragma unroll
    for (int mt = 0; mt < 4; mt++) {
#pragma unroll
        for (int nt = 0; nt < 4; nt++) {
            int row0 = bm + warpM * 64 + mt * 16 + gp;
            int col0 = bn + warpN * 32 + nt * 8 + lq * 2;
#pragma unroll
            for (int v = 0; v < 4; v++) {
                int row = row0 + (v >> 1) * 8;
                int col = col0 + (v & 1);
                if (row < M && col < N) {
                    float val = acc[mt][nt][v] + bias[col];
                    if (do_relu) val = fmaxf(val, 0.f);
                    Cout[(size_t)row * ldc + col] = val;
                }
            }
        }
    }
}

// Copy init (= result[:, 0, :]) to the tail of d_out (second tuple output).
__global__ void copy_init_tail_kernel(float* __restrict__ out)
{
    int i = blockIdx.x * blockDim.x + threadIdx.x;
    if (i >= B_ * C_) return;
    int b = i / C_;
    int c = i - b * C_;
    out[(size_t)B_ * T_ * C_ + i] = out[(size_t)b * T_ * C_ + c];
}

// ---------------------------------------------------------------------------
static inline void gemm(const float* A, const float* W, const float* bias,
                        float* C, int M, int N, int K, int ldc, bool relu,
                        int mode = 0, const float* src = nullptr,
                        const float* prevOut = nullptr, int t = 0)
{
    dim3 grid((N + BN - 1) / BN, (M + BM - 1) / BM);
    gemm_tf32_kernel<<<grid, 256>>>(A, W, bias, C, M, N, K, ldc, relu ? 1 : 0,
                                    mode, src, prevOut, t);
}

extern "C" void kernel_launch(void* const* d_in, const int* in_sizes, int n_in,
                              void* d_out, int out_size)
{
    const float* src  = (const float*)d_in[0];
    const float* wi1  = (const float*)d_in[1];
    const float* bi1  = (const float*)d_in[2];
    const float* wi2  = (const float*)d_in[3];
    const float* bi2  = (const float*)d_in[4];
    const float* wi25 = (const float*)d_in[5];
    const float* bi25 = (const float*)d_in[6];
    const float* wi3  = (const float*)d_in[7];
    const float* bi3  = (const float*)d_in[8];
    const float* w1   = (const float*)d_in[9];
    const float* b1   = (const float*)d_in[10];
    const float* w12  = (const float*)d_in[11];
    const float* b12  = (const float*)d_in[12];
    const float* w2   = (const float*)d_in[13];
    const float* b2   = (const float*)d_in[14];
    const float* w22  = (const float*)d_in[15];
    const float* b22  = (const float*)d_in[16];
    const float* w3   = (const float*)d_in[17];
    const float* b3   = (const float*)d_in[18];
    const float* w4   = (const float*)d_in[19];
    const float* b4   = (const float*)d_in[20];
    const float* w4d  = (const float*)d_in[21];
    const float* b4d  = (const float*)d_in[22];

    float* out = (float*)d_out;

    float* bufA = nullptr;
    float* bufB = nullptr;
    cudaGetSymbolAddress((void**)&bufA, g_bufA);
    cudaGetSymbolAddress((void**)&bufB, g_bufB);

    const int FEAT = 2 * F_ + C_;   // 141
    const int LDO  = T_ * C_;       // output row stride (per batch)

    // ---- getInitialPos: (B, T*F=3060) -> 2048 -> 1024 -> 512 -> 69
    gemm(src,  wi1,  bi1,  bufA, B_, 4 * H_, T_ * F_, 4 * H_, true);
    gemm(bufA, wi2,  bi2,  bufB, B_, 2 * H_, 4 * H_, 2 * H_, true);
    gemm(bufB, wi25, bi25, bufA, B_, H_,     2 * H_, H_,     false);
    gemm(bufA, wi3,  bi3,  out,  B_, C_,     H_,     LDO,    false);   // result[:,0,:]

    // ---- scan: 84 sequential steps of the 7-layer "follow" MLP
    for (int t = 1; t < T_; t++) {
        // layer 1 with fused concat-gather A operand
        gemm(nullptr, w1, b1, bufA, B_, 4 * H_, FEAT, 4 * H_, true,
             1, src, out, t);
        gemm(bufA, w12, b12, bufB, B_, 4 * H_, 4 * H_, 4 * H_, true);
        gemm(bufB, w2,  b2,  bufA, B_, 2 * H_, 4 * H_, 2 * H_, true);
        gemm(bufA, w22, b22, bufB, B_, 2 * H_, 2 * H_, 2 * H_, true);
        gemm(bufB, w3,  b3,  bufA, B_, H_,     2 * H_, H_,     true);
        gemm(bufA, w4,  b4,  bufB, B_, H_,     H_,     H_,     false);
        gemm(bufB, w4d, b4d, out + (size_t)t * C_, B_, C_, H_, LDO, false);
    }

    // ---- second tuple output (init), if present in d_out
    if (out_size >= B_ * T_ * C_ + B_ * C_) {
        copy_init_tail_kernel<<<(B_ * C_ + 255) / 256, 256>>>(out);
    }
}

// round 3
// speedup vs baseline: 3.0610x; 2.1310x over previous
#include <cuda_runtime.h>
#include <cstdint>
#include <cstddef>

// Problem constants
#define B_  1024
#define T_  85
#define F_  36
#define H_  512
#define C_  69

// Scratch activations
__device__ float g_bufA[B_ * 4 * H_];
__device__ float g_bufB[B_ * 4 * H_];

// Pre-rounded (TF32) weights + source, packed. Offsets below.
#define OFF_WI1  0u
#define OFF_WI2  6266880u
#define OFF_WI25 8364032u
#define OFF_WI3  8888320u
#define OFF_W1   8923648u
#define OFF_W12  9212416u
#define OFF_W2   13406720u
#define OFF_W22  15503872u
#define OFF_W3   16552448u
#define OFF_W4   17076736u
#define OFF_W4D  17338880u
#define OFF_SRC  17374208u
#define WR_TOTAL 20507648u
__device__ float g_wr[WR_TOTAL];

__device__ __forceinline__ uint32_t f2tf32(float x) {
    uint32_t r;
    asm("cvt.rna.tf32.f32 %0, %1;" : "=r"(r) : "f"(x));
    return r;
}

__device__ __forceinline__ void mma_tf32(float (&d)[4],
                                         const uint32_t (&a)[4],
                                         const uint32_t (&b)[2]) {
    asm volatile(
        "mma.sync.aligned.m16n8k8.row.col.f32.tf32.tf32.f32 "
        "{%0,%1,%2,%3}, {%4,%5,%6,%7}, {%8,%9}, {%0,%1,%2,%3};"
        : "+f"(d[0]), "+f"(d[1]), "+f"(d[2]), "+f"(d[3])
        : "r"(a[0]), "r"(a[1]), "r"(a[2]), "r"(a[3]),
          "r"(b[0]), "r"(b[1]));
}

// Round fp32 -> tf32 bits, vectorized.
__global__ void round4_kernel(const float4* __restrict__ in,
                              float4* __restrict__ outp, int n4)
{
    int i = blockIdx.x * blockDim.x + threadIdx.x;
    if (i >= n4) return;
    float4 v = in[i];
    v.x = __uint_as_float(f2tf32(v.x));
    v.y = __uint_as_float(f2tf32(v.y));
    v.z = __uint_as_float(f2tf32(v.z));
    v.w = __uint_as_float(f2tf32(v.w));
    outp[i] = v;
}

// ---------------------------------------------------------------------------
// Pipelined TF32 GEMM: C = act(A @ W + bias); A MxK rm, W KxN rm (pre-rounded)
// 2-stage cp.async double buffering. 256 threads, 8 warps.
// flags: bit0 = relu, bit1 = round output to tf32 (for scratch activations).
// GATHER: A = concat(srcr[:,t-1,:], srcr[:,t,:], prevOut[:,t-1,:]) per row.
// ---------------------------------------------------------------------------
#define BK 16

template<int BM, int BN, int WM, int WN, bool GATHER>
__global__ __launch_bounds__(256)
void gemm_tf32_pipe(const float* __restrict__ A,
                    const float* __restrict__ W,
                    const float* __restrict__ bias,
                    float* __restrict__ Cout,
                    int M, int N, int K, int ldc, int flags,
                    const float* __restrict__ srcr,
                    const float* __restrict__ prevOut, int t)
{
    constexpr int MT = BM / WM / 16;
    constexpr int NT = BN / WN / 8;
    constexpr int ASTR = BK + 4;     // 20 floats: conflict-free A frag loads
    constexpr int BSTR = BN + 8;     // conflict-free B frag loads

    __shared__ __align__(16) float As[2][BM][ASTR];
    __shared__ __align__(16) float Bs[2][BK][BSTR];

    const int bm   = blockIdx.y * BM;
    const int bn   = blockIdx.x * BN;
    const int tid  = threadIdx.x;
    const int lane = tid & 31;
    const int wid  = tid >> 5;
    const int warpM = wid / WN;
    const int warpN = wid % WN;
    const int gp = lane >> 2;
    const int lq = lane & 3;

    const int iters = (K + BK - 1) / BK;

    auto fetchA = [&](int st, int k0) {
        if (GATHER) {
            constexpr int TOT = BM * BK;
#pragma unroll
            for (int i = 0; i < TOT / 256; i++) {
                int idx = i * 256 + tid;
                int row = idx >> 4;
                int kc  = idx & 15;
                int gk  = k0 + kc;
                int gr  = bm + row;
                float v = 0.f;
                if (gk < 2 * F_) {
                    int tt = (gk < F_) ? (t - 1) : t;
                    int ff = (gk < F_) ? gk : gk - F_;
                    v = srcr[(size_t)gr * T_ * F_ + (size_t)tt * F_ + ff];
                } else if (gk < K) {
                    v = __uint_as_float(f2tf32(
                        prevOut[(size_t)gr * T_ * C_ + (size_t)(t - 1) * C_ + (gk - 2 * F_)]));
                }
                As[st][row][kc] = v;
            }
        } else {
            constexpr int CH = BM * 4;   // 16B chunks in A tile
#pragma unroll
            for (int i = 0; i < CH / 256; i++) {
                int c   = i * 256 + tid;
                int row = c >> 2;
                int off = (c & 3) * 4;
                int gk0 = k0 + off;
                int rem = K - gk0;
                int bytes = rem >= 4 ? 16 : (rem > 0 ? rem * 4 : 0);
                int gks = gk0 < K ? gk0 : 0;
                const float* gptr = A + (size_t)(bm + row) * K + gks;
                uint32_t dst = (uint32_t)__cvta_generic_to_shared(&As[st][row][off]);
                asm volatile("cp.async.ca.shared.global [%0], [%1], 16, %2;\n"
                             :: "r"(dst), "l"(gptr), "r"(bytes));
            }
        }
    };

    auto fetchB = [&](int st, int k0) {
        if ((N & 3) == 0) {
            constexpr int CH = BK * BN / 4;
#pragma unroll
            for (int i = 0; i < CH / 256; i++) {
                int c   = i * 256 + tid;
                int row = c / (BN / 4);
                int col = (c % (BN / 4)) * 4;
                int gk  = k0 + row;
                int bytes = (gk < K) ? 16 : 0;
                int gks = gk < K ? gk : 0;
                const float* gptr = W + (size_t)gks * N + bn + col;
                uint32_t dst = (uint32_t)__cvta_generic_to_shared(&Bs[st][row][col]);
                asm volatile("cp.async.ca.shared.global [%0], [%1], 16, %2;\n"
                             :: "r"(dst), "l"(gptr), "r"(bytes));
            }
        } else {
            constexpr int TOT = BK * BN;
#pragma unroll
            for (int i = 0; i < TOT / 256; i++) {
                int idx = i * 256 + tid;
                int row = idx / BN;
                int col = idx % BN;
                int gk = k0 + row, gc = bn + col;
                float v = 0.f;
                if (gk < K && gc < N) v = W[(size_t)gk * N + gc];
                Bs[st][row][col] = v;
            }
        }
    };

    float acc[MT][NT][4];
#pragma unroll
    for (int i = 0; i < MT; i++)
#pragma unroll
        for (int j = 0; j < NT; j++)
#pragma unroll
            for (int v = 0; v < 4; v++) acc[i][j][v] = 0.f;

    fetchA(0, 0);
    fetchB(0, 0);
    asm volatile("cp.async.commit_group;\n" ::: "memory");

    for (int i = 0; i < iters; i++) {
        if (i + 1 < iters) {
            fetchA((i + 1) & 1, (i + 1) * BK);
            fetchB((i + 1) & 1, (i + 1) * BK);
        }
        asm volatile("cp.async.commit_group;\n" ::: "memory");
        asm volatile("cp.async.wait_group 1;\n" ::: "memory");
        __syncthreads();

        const int st = i & 1;
#pragma unroll
        for (int kk = 0; kk < BK; kk += 8) {
            uint32_t af[MT][4];
            uint32_t bf[NT][2];
#pragma unroll
            for (int mt = 0; mt < MT; mt++) {
                int r0 = warpM * (BM / WM) + mt * 16 + gp;
                af[mt][0] = __float_as_uint(As[st][r0][kk + lq]);
                af[mt][1] = __float_as_uint(As[st][r0 + 8][kk + lq]);
                af[mt][2] = __float_as_uint(As[st][r0][kk + lq + 4]);
                af[mt][3] = __float_as_uint(As[st][r0 + 8][kk + lq + 4]);
            }
#pragma unroll
            for (int nt = 0; nt < NT; nt++) {
                int c0 = warpN * (BN / WN) + nt * 8 + gp;
                bf[nt][0] = __float_as_uint(Bs[st][kk + lq][c0]);
                bf[nt][1] = __float_as_uint(Bs[st][kk + lq + 4][c0]);
            }
#pragma unroll
            for (int mt = 0; mt < MT; mt++)
#pragma unroll
                for (int nt = 0; nt < NT; nt++)
                    mma_tf32(acc[mt][nt], af[mt], bf[nt]);
        }
        __syncthreads();
    }

    // Epilogue: bias + relu (+ tf32 round for scratch), strided store.
    const bool relu = flags & 1;
    const bool rnd  = flags & 2;
#pragma unroll
    for (int mt = 0; mt < MT; mt++) {
#pragma unroll
        for (int nt = 0; nt < NT; nt++) {
            int row0 = bm + warpM * (BM / WM) + mt * 16 + gp;
            int col0 = bn + warpN * (BN / WN) + nt * 8 + lq * 2;
#pragma unroll
            for (int v = 0; v < 4; v++) {
                int row = row0 + (v >> 1) * 8;
                int col = col0 + (v & 1);
                if (row < M && col < N) {
                    float val = acc[mt][nt][v] + bias[col];
                    if (relu) val = fmaxf(val, 0.f);
                    if (rnd)  val = __uint_as_float(f2tf32(val));
                    Cout[(size_t)row * ldc + col] = val;
                }
            }
        }
    }
}

// Copy init (= result[:, 0, :]) to the tail of d_out (second tuple output).
__global__ void copy_init_tail_kernel(float* __restrict__ out)
{
    int i = blockIdx.x * blockDim.x + threadIdx.x;
    if (i >= B_ * C_) return;
    int b = i / C_;
    int c = i - b * C_;
    out[(size_t)B_ * T_ * C_ + i] = out[(size_t)b * T_ * C_ + c];
}

// ---------------------------------------------------------------------------
template<int BM, int BN, int WM, int WN, bool G>
static void launch_gemm(const float* A, const float* W, const float* bias,
                        float* C, int M, int N, int K, int ldc, int flags,
                        const float* srcr = nullptr,
                        const float* prevOut = nullptr, int t = 0)
{
    dim3 grid((N + BN - 1) / BN, (M + BM - 1) / BM);
    gemm_tf32_pipe<BM, BN, WM, WN, G><<<grid, 256>>>(
        A, W, bias, C, M, N, K, ldc, flags, srcr, prevOut, t);
}

static void round_to(const float* in, float* outp, size_t n)
{
    int n4 = (int)(n / 4);
    round4_kernel<<<(n4 + 511) / 512, 512>>>((const float4*)in, (float4*)outp, n4);
}

extern "C" void kernel_launch(void* const* d_in, const int* in_sizes, int n_in,
                              void* d_out, int out_size)
{
    const float* src  = (const float*)d_in[0];
    const float* wi1  = (const float*)d_in[1];
    const float* bi1  = (const float*)d_in[2];
    const float* wi2  = (const float*)d_in[3];
    const float* bi2  = (const float*)d_in[4];
    const float* wi25 = (const float*)d_in[5];
    const float* bi25 = (const float*)d_in[6];
    const float* wi3  = (const float*)d_in[7];
    const float* bi3  = (const float*)d_in[8];
    const float* w1   = (const float*)d_in[9];
    const float* b1   = (const float*)d_in[10];
    const float* w12  = (const float*)d_in[11];
    const float* b12  = (const float*)d_in[12];
    const float* w2   = (const float*)d_in[13];
    const float* b2   = (const float*)d_in[14];
    const float* w22  = (const float*)d_in[15];
    const float* b22  = (const float*)d_in[16];
    const float* w3   = (const float*)d_in[17];
    const float* b3   = (const float*)d_in[18];
    const float* w4   = (const float*)d_in[19];
    const float* b4   = (const float*)d_in[20];
    const float* w4d  = (const float*)d_in[21];
    const float* b4d  = (const float*)d_in[22];

    float* out = (float*)d_out;

    float* bufA = nullptr; float* bufB = nullptr; float* wr = nullptr;
    cudaGetSymbolAddress((void**)&bufA, g_bufA);
    cudaGetSymbolAddress((void**)&bufB, g_bufB);
    cudaGetSymbolAddress((void**)&wr,   g_wr);

    // ---- pre-round weights + src to TF32 (loop-invariant) ----
    round_to(wi1,  wr + OFF_WI1,  3060u * 2048u);
    round_to(wi2,  wr + OFF_WI2,  2048u * 1024u);
    round_to(wi25, wr + OFF_WI25, 1024u * 512u);
    round_to(wi3,  wr + OFF_WI3,  512u * 69u);
    round_to(w1,   wr + OFF_W1,   141u * 2048u);
    round_to(w12,  wr + OFF_W12,  2048u * 2048u);
    round_to(w2,   wr + OFF_W2,   2048u * 1024u);
    round_to(w22,  wr + OFF_W22,  1024u * 1024u);
    round_to(w3,   wr + OFF_W3,   1024u * 512u);
    round_to(w4,   wr + OFF_W4,   512u * 512u);
    round_to(w4d,  wr + OFF_W4D,  512u * 69u);
    round_to(src,  wr + OFF_SRC,  (size_t)B_ * T_ * F_);

    const float* srcr = wr + OFF_SRC;
    const int LDO = T_ * C_;

    // ---- getInitialPos: 3060 -> 2048 -> 1024 -> 512 -> 69
    launch_gemm<128,128,2,4,false>(srcr, wr + OFF_WI1,  bi1,  bufA, B_, 4*H_, T_*F_, 4*H_, 3);
    launch_gemm< 64,128,2,4,false>(bufA, wr + OFF_WI2,  bi2,  bufB, B_, 2*H_, 4*H_,  2*H_, 3);
    launch_gemm< 64, 64,4,2,false>(bufB, wr + OFF_WI25, bi25, bufA, B_, H_,   2*H_,  H_,   2);
    launch_gemm< 64, 64,4,2,false>(bufA, wr + OFF_WI3,  bi3,  out,  B_, C_,   H_,    LDO,  0);

    // ---- scan: 84 sequential steps
    const int FEAT = 2 * F_ + C_;   // 141
    for (int t = 1; t < T_; t++) {
        launch_gemm<128,128,2,4,true >(nullptr, wr + OFF_W1, b1, bufA, B_, 4*H_, FEAT, 4*H_, 3,
                                       srcr, out, t);
        launch_gemm<128,128,2,4,false>(bufA, wr + OFF_W12, b12, bufB, B_, 4*H_, 4*H_, 4*H_, 3);
        launch_gemm< 64,128,2,4,false>(bufB, wr + OFF_W2,  b2,  bufA, B_, 2*H_, 4*H_, 2*H_, 3);
        launch_gemm< 64,128,2,4,false>(bufA, wr + OFF_W22, b22, bufB, B_, 2*H_, 2*H_, 2*H_, 3);
        launch_gemm< 64, 64,4,2,false>(bufB, wr + OFF_W3,  b3,  bufA, B_, H_,   2*H_, H_,   3);
        launch_gemm< 64, 64,4,2,false>(bufA, wr + OFF_W4,  b4,  bufB, B_, H_,   H_,   H_,   2);
        launch_gemm< 64, 64,4,2,false>(bufB, wr + OFF_W4D, b4d, out + (size_t)t * C_,
                                       B_, C_, H_, LDO, 0);
    }

    // ---- second tuple output (init), if present
    if (out_size >= B_ * T_ * C_ + B_ * C_) {
        copy_init_tail_kernel<<<(B_ * C_ + 255) / 256, 256>>>(out);
    }
}

// round 5
// speedup vs baseline: 5.9995x; 1.9600x over previous
#include <cuda_runtime.h>
#include <cuda_fp16.h>
#include <cstdint>
#include <cstddef>

// Problem constants
#define B_  1024
#define T_  85
#define F_  36
#define H_  512
#define C_  69

// ---------------------------------------------------------------------------
// Device globals (no runtime allocation allowed)
// ---------------------------------------------------------------------------
__device__ __half g_hA[B_ * 4 * H_];            // activation ping
__device__ __half g_hB[B_ * 4 * H_];            // activation pong
__device__ __half g_srch[B_ * 3072];            // fp16 source, row-padded to 3072
__device__ float  g_bc[2 * C_];                 // composed biases: [0..C) follow, [C..2C) init

// Transposed (K-major, [N][Kp]) fp16 weights, packed (offsets in halfs)
#define OFF_WI1T    0u          /* 2048 x 3072 */
#define OFF_WI2T    6291456u    /* 1024 x 2048 */
#define OFF_WI25CT  8388608u    /* 69   x 1024 */
#define OFF_W1T     8459264u    /* 2048 x 160  */
#define OFF_W12T    8786944u    /* 2048 x 2048 */
#define OFF_W2T     12981248u   /* 1024 x 2048 */
#define OFF_W22T    15078400u   /* 1024 x 1024 */
#define OFF_W3T     16126976u   /* 512  x 1024 */
#define OFF_W4CT    16651264u   /* 69   x 512  */
#define WH_TOTAL    16686592u
__device__ __half g_wh[WH_TOTAL];

// ---------------------------------------------------------------------------
__device__ __forceinline__ void mma_f16(float (&d)[4],
                                        const uint32_t (&a)[4],
                                        const uint32_t (&b)[2]) {
    asm volatile(
        "mma.sync.aligned.m16n8k16.row.col.f32.f16.f16.f32 "
        "{%0,%1,%2,%3}, {%4,%5,%6,%7}, {%8,%9}, {%0,%1,%2,%3};"
        : "+f"(d[0]), "+f"(d[1]), "+f"(d[2]), "+f"(d[3])
        : "r"(a[0]), "r"(a[1]), "r"(a[2]), "r"(a[3]),
          "r"(b[0]), "r"(b[1]));
}

// ---------------------------------------------------------------------------
// FP16 tensor GEMM: C[M,N] = act(A[M,K] @ Wt[N,Kp]^T + bias)
// A: fp16 [M][lda] row-major; Wt: fp16 [N][Kp] K-major. BK=32, 2-stage cp.async.
// 8 warps as 2x4; warp tile (BM/2, BN/4). flags: bit0 relu, bit1 fp16 output.
// GATHER: A row b = concat(srch[b,t-1,:F], srch[b,t,:F], h(prevOut[b,t-1,:C]))
// ---------------------------------------------------------------------------
#define BK 32
#define ASTR 40   // halfs per smem row (32 data + 8 pad) -> conflict-free

template<int BM, int BN, bool GATHER>
__global__ __launch_bounds__(256)
void gemm_f16_kernel(const __half* __restrict__ A,
                     const __half* __restrict__ Wt,
                     const float* __restrict__ bias,
                     void* __restrict__ Cout,
                     int M, int N, int K, int Kp, int lda, int ldc, int flags,
                     const __half* __restrict__ srch,
                     const float* __restrict__ prevOut, int t)
{
    constexpr int MT = BM / 32;       // m16 tiles per warp
    constexpr int NT = BN / 32;       // n8 tiles per warp

    __shared__ __align__(16) __half As[2][BM][ASTR];
    __shared__ __align__(16) __half Bs[2][BN][ASTR];

    const int bm   = blockIdx.y * BM;
    const int bn   = blockIdx.x * BN;
    const int tid  = threadIdx.x;
    const int lane = tid & 31;
    const int wid  = tid >> 5;
    const int warpM = wid >> 2;       // 0..1
    const int warpN = wid & 3;        // 0..3
    const int gp = lane >> 2;         // 0..7
    const int lq = lane & 3;          // 0..3

    const int KT = (K + BK - 1) / BK;

    auto fetchA = [&](int st, int kt) {
        if (GATHER) {
            constexpr int TOT = BM * 32;
#pragma unroll
            for (int i = 0; i < TOT / 256; i++) {
                int e   = i * 256 + tid;
                int row = e >> 5;
                int kc  = e & 31;
                int gk  = kt * 32 + kc;
                int gr  = bm + row;
                __half v = __float2half(0.f);
                if (gk < 2 * F_) {
                    int tt = (gk < F_) ? (t - 1) : t;
                    int ff = (gk < F_) ? gk : gk - F_;
                    v = srch[(size_t)gr * 3072 + tt * F_ + ff];
                } else if (gk < K) {
                    v = __float2half(
                        prevOut[(size_t)gr * T_ * C_ + (size_t)(t - 1) * C_ + (gk - 2 * F_)]);
                }
                As[st][row][kc] = v;
            }
        } else {
            constexpr int CH = BM * 4;        // 16B chunks (8 halfs each)
#pragma unroll
            for (int i = 0; i < CH / 256; i++) {
                int c   = i * 256 + tid;
                int row = c >> 2;
                int ch  = c & 3;
                int gk0 = kt * 32 + ch * 8;
                int rem = K - gk0;
                int bytes = rem >= 8 ? 16 : (rem > 0 ? rem * 2 : 0);
                const __half* g = A + (size_t)(bm + row) * lda + (gk0 < K ? gk0 : 0);
                uint32_t dst = (uint32_t)__cvta_generic_to_shared(&As[st][row][ch * 8]);
                asm volatile("cp.async.ca.shared.global [%0], [%1], 16, %2;"
                             :: "r"(dst), "l"(g), "r"(bytes));
            }
        }
    };

    auto fetchB = [&](int st, int kt) {
        constexpr int CH = BN * 4;
#pragma unroll
        for (int i = 0; i < CH / 256; i++) {
            int c   = i * 256 + tid;
            int row = c >> 2;
            int ch  = c & 3;
            int gn  = bn + row;
            int bytes = (gn < N) ? 16 : 0;
            const __half* g = Wt + (size_t)(gn < N ? gn : 0) * Kp + kt * 32 + ch * 8;
            uint32_t dst = (uint32_t)__cvta_generic_to_shared(&Bs[st][row][ch * 8]);
            asm volatile("cp.async.ca.shared.global [%0], [%1], 16, %2;"
                         :: "r"(dst), "l"(g), "r"(bytes));
        }
    };

    float acc[MT][NT][4];
#pragma unroll
    for (int i = 0; i < MT; i++)
#pragma unroll
        for (int j = 0; j < NT; j++)
#pragma unroll
            for (int v = 0; v < 4; v++) acc[i][j][v] = 0.f;

    fetchA(0, 0);
    fetchB(0, 0);
    asm volatile("cp.async.commit_group;" ::: "memory");

    for (int kt = 0; kt < KT; kt++) {
        if (kt + 1 < KT) {
            fetchA((kt + 1) & 1, kt + 1);
            fetchB((kt + 1) & 1, kt + 1);
        }
        asm volatile("cp.async.commit_group;" ::: "memory");
        asm volatile("cp.async.wait_group 1;" ::: "memory");
        __syncthreads();

        const int st = kt & 1;
#pragma unroll
        for (int kk = 0; kk < BK; kk += 16) {
            uint32_t af[MT][4];
            uint32_t bf[NT][2];
#pragma unroll
            for (int mt = 0; mt < MT; mt++) {
                int r0 = warpM * (BM / 2) + mt * 16 + gp;
                af[mt][0] = *(const uint32_t*)&As[st][r0][kk + 2 * lq];
                af[mt][1] = *(const uint32_t*)&As[st][r0 + 8][kk + 2 * lq];
                af[mt][2] = *(const uint32_t*)&As[st][r0][kk + 2 * lq + 8];
                af[mt][3] = *(const uint32_t*)&As[st][r0 + 8][kk + 2 * lq + 8];
            }
#pragma unroll
            for (int nt = 0; nt < NT; nt++) {
                int c0 = warpN * (BN / 4) + nt * 8 + gp;
                bf[nt][0] = *(const uint32_t*)&Bs[st][c0][kk + 2 * lq];
                bf[nt][1] = *(const uint32_t*)&Bs[st][c0][kk + 2 * lq + 8];
            }
#pragma unroll
            for (int mt = 0; mt < MT; mt++)
#pragma unroll
                for (int nt = 0; nt < NT; nt++)
                    mma_f16(acc[mt][nt], af[mt], bf[nt]);
        }
        __syncthreads();
    }

    // ---- epilogue ----
    const bool relu = flags & 1;
    const bool houT = flags & 2;
#pragma unroll
    for (int mt = 0; mt < MT; mt++) {
#pragma unroll
        for (int nt = 0; nt < NT; nt++) {
            int row0 = bm + warpM * (BM / 2) + mt * 16 + gp;
            int col0 = bn + warpN * (BN / 4) + nt * 8 + lq * 2;
            float b0 = (col0 < N)     ? bias[col0]     : 0.f;
            float b1 = (col0 + 1 < N) ? bias[col0 + 1] : 0.f;
            float x0 = acc[mt][nt][0] + b0;
            float x1 = acc[mt][nt][1] + b1;
            float x2 = acc[mt][nt][2] + b0;
            float x3 = acc[mt][nt][3] + b1;
            if (relu) {
                x0 = fmaxf(x0, 0.f); x1 = fmaxf(x1, 0.f);
                x2 = fmaxf(x2, 0.f); x3 = fmaxf(x3, 0.f);
            }
            if (houT) {
                __half* cp = (__half*)Cout;
                *(__half2*)(cp + (size_t)row0 * ldc + col0) = __floats2half2_rn(x0, x1);
                *(__half2*)(cp + (size_t)(row0 + 8) * ldc + col0) = __floats2half2_rn(x2, x3);
            } else {
                float* cp = (float*)Cout;
                if (col0 < N) {
                    cp[(size_t)row0 * ldc + col0] = x0;
                    cp[(size_t)(row0 + 8) * ldc + col0] = x2;
                }
                if (col0 + 1 < N) {
                    cp[(size_t)row0 * ldc + col0 + 1] = x1;
                    cp[(size_t)(row0 + 8) * ldc + col0 + 1] = x3;
                }
            }
        }
    }
}

// ---------------------------------------------------------------------------
// Prep kernels (run once per replay; cheap)
// ---------------------------------------------------------------------------
// Source fp32 -> fp16, row-padded [B][3072]
__global__ void src_round_kernel(const float* __restrict__ src,
                                 __half* __restrict__ dst)
{
    int i = blockIdx.x * blockDim.x + threadIdx.x;
    if (i >= B_ * 3072) return;
    int b = i >> 11;                 // /3072? 3072 = 3*1024, not power of 2
    b = i / 3072;
    int j = i - b * 3072;
    float v = (j < T_ * F_) ? src[(size_t)b * T_ * F_ + j] : 0.f;
    dst[i] = __float2half(v);
}

// W [K][N] fp32 -> Wt [N][Kp] fp16 (K-major, zero-padded)
__global__ void transpose_h_kernel(const float* __restrict__ W,
                                   __half* __restrict__ Wt,
                                   int K, int N, int Kp)
{
    __shared__ float tile[32][33];
    int k0 = blockIdx.x * 32;
    int n0 = blockIdx.y * 32;
    int tx = threadIdx.x, ty = threadIdx.y;   // 32 x 8
    for (int i = ty; i < 32; i += 8) {
        int k = k0 + i, n = n0 + tx;
        tile[i][tx] = (k < K && n < N) ? W[(size_t)k * N + n] : 0.f;
    }
    __syncthreads();
    for (int i = ty; i < 32; i += 8) {
        int n = n0 + i, k = k0 + tx;
        if (n < N && k < Kp)
            Wt[(size_t)n * Kp + k] = __float2half(tile[tx][i]);
    }
}

// Compose Wc = W1[D][I] @ W2[I][N], store transposed fp16 [N][D]. One block per d.
__global__ void compose_w_kernel(const float* __restrict__ W1,
                                 const float* __restrict__ W2,
                                 __half* __restrict__ outT,
                                 int D, int I, int N)
{
    __shared__ float row[512];
    int d = blockIdx.x;
    for (int i = threadIdx.x; i < I; i += 128) row[i] = W1[(size_t)d * I + i];
    __syncthreads();
    for (int n = threadIdx.x; n < N; n += 128) {
        float s = 0.f;
        for (int i = 0; i < I; i++) s += row[i] * W2[(size_t)i * N + n];
        outT[(size_t)n * D + d] = __float2half(s);
    }
}

// bc[n] = sum_i b1[i] * W2[i][n] + b2[n]
__global__ void compose_bias_kernel(const float* __restrict__ b1,
                                    const float* __restrict__ W2,
                                    const float* __restrict__ b2,
                                    float* __restrict__ bc, int I, int N)
{
    int n = threadIdx.x;
    if (n >= N) return;
    float s = b2[n];
    for (int i = 0; i < I; i++) s += b1[i] * W2[(size_t)i * N + n];
    bc[n] = s;
}

__global__ void copy_init_tail_kernel(float* __restrict__ out)
{
    int i = blockIdx.x * blockDim.x + threadIdx.x;
    if (i >= B_ * C_) return;
    int b = i / C_;
    int c = i - b * C_;
    out[(size_t)B_ * T_ * C_ + i] = out[(size_t)b * T_ * C_ + c];
}

// ---------------------------------------------------------------------------
template<int BM, int BN, bool G>
static void launch_gemm(const __half* A, const __half* Wt, const float* bias,
                        void* C, int M, int N, int K, int Kp, int lda, int ldc,
                        int flags, const __half* srch = nullptr,
                        const float* prevOut = nullptr, int t = 0)
{
    dim3 grid((N + BN - 1) / BN, M / BM);
    gemm_f16_kernel<BM, BN, G><<<grid, 256>>>(
        A, Wt, bias, C, M, N, K, Kp, lda, ldc, flags, srch, prevOut, t);
}

static void trsp(const float* W, __half* Wt, int K, int N, int Kp)
{
    dim3 grid(Kp / 32, (N + 31) / 32);
    transpose_h_kernel<<<grid, dim3(32, 8)>>>(W, Wt, K, N, Kp);
}

extern "C" void kernel_launch(void* const* d_in, const int* in_sizes, int n_in,
                              void* d_out, int out_size)
{
    const float* src  = (const float*)d_in[0];
    const float* wi1  = (const float*)d_in[1];
    const float* bi1  = (const float*)d_in[2];
    const float* wi2  = (const float*)d_in[3];
    const float* bi2  = (const float*)d_in[4];
    const float* wi25 = (const float*)d_in[5];
    const float* bi25 = (const float*)d_in[6];
    const float* wi3  = (const float*)d_in[7];
    const float* bi3  = (const float*)d_in[8];
    const float* w1   = (const float*)d_in[9];
    const float* b1   = (const float*)d_in[10];
    const float* w12  = (const float*)d_in[11];
    const float* b12  = (const float*)d_in[12];
    const float* w2   = (const float*)d_in[13];
    const float* b2   = (const float*)d_in[14];
    const float* w22  = (const float*)d_in[15];
    const float* b22  = (const float*)d_in[16];
    const float* w3   = (const float*)d_in[17];
    const float* b3   = (const float*)d_in[18];
    const float* w4   = (const float*)d_in[19];
    const float* b4   = (const float*)d_in[20];
    const float* w4d  = (const float*)d_in[21];
    const float* b4d  = (const float*)d_in[22];

    float* out = (float*)d_out;

    __half *hA = nullptr, *hB = nullptr, *srch = nullptr, *wh = nullptr;
    float* bc = nullptr;
    cudaGetSymbolAddress((void**)&hA,   g_hA);
    cudaGetSymbolAddress((void**)&hB,   g_hB);
    cudaGetSymbolAddress((void**)&srch, g_srch);
    cudaGetSymbolAddress((void**)&wh,   g_wh);
    cudaGetSymbolAddress((void**)&bc,   g_bc);

    // ---- prep: fp16 transposed weights, composed linear pairs, fp16 source ----
    trsp(wi1, wh + OFF_WI1T, 3060, 2048, 3072);
    trsp(wi2, wh + OFF_WI2T, 2048, 1024, 2048);
    trsp(w1,  wh + OFF_W1T,  141,  2048, 160);
    trsp(w12, wh + OFF_W12T, 2048, 2048, 2048);
    trsp(w2,  wh + OFF_W2T,  2048, 1024, 2048);
    trsp(w22, wh + OFF_W22T, 1024, 1024, 1024);
    trsp(w3,  wh + OFF_W3T,  1024, 512,  1024);
    // composed: wi25c = wi25 @ wi3 (1024 x 69), w4c = w4 @ w4d (512 x 69)
    compose_w_kernel<<<1024, 128>>>(wi25, wi3, wh + OFF_WI25CT, 1024, 512, C_);
    compose_w_kernel<<<512,  128>>>(w4,   w4d, wh + OFF_W4CT,   512,  512, C_);
    compose_bias_kernel<<<1, 128>>>(b4,   w4d, b4d, bc,      512, C_);
    compose_bias_kernel<<<1, 128>>>(bi25, wi3, bi3, bc + C_, 512, C_);
    src_round_kernel<<<(B_ * 3072 + 511) / 512, 512>>>(src, srch);

    const int LDO = T_ * C_;
    const int FEAT = 2 * F_ + C_;   // 141

    // flags: 1 relu | 2 fp16 output
    // ---- getInitialPos: 3060 -> 2048 -> 1024 -> 69 (wi25∘wi3 composed)
    launch_gemm<128,128,false>(srch, wh + OFF_WI1T, bi1, hA,
                               B_, 2048, 3060, 3072, 3072, 2048, 3);
    launch_gemm<64,128,false>(hA, wh + OFF_WI2T, bi2, hB,
                              B_, 1024, 2048, 2048, 2048, 1024, 3);
    launch_gemm<64,64,false>(hB, wh + OFF_WI25CT, bc + C_, out,
                             B_, C_, 1024, 1024, 1024, LDO, 0);

    // ---- scan: 84 steps x 6 GEMMs (w4∘w4d composed)
    for (int t = 1; t < T_; t++) {
        launch_gemm<128,128,true>(nullptr, wh + OFF_W1T, b1, hA,
                                  B_, 2048, FEAT, 160, 0, 2048, 3, srch, out, t);
        launch_gemm<128,128,false>(hA, wh + OFF_W12T, b12, hB,
                                   B_, 2048, 2048, 2048, 2048, 2048, 3);
        launch_gemm<64,128,false>(hB, wh + OFF_W2T, b2, hA,
                                  B_, 1024, 2048, 2048, 2048, 1024, 3);
        launch_gemm<64,128,false>(hA, wh + OFF_W22T, b22, hB,
                                  B_, 1024, 1024, 1024, 1024, 1024, 3);
        launch_gemm<64,64,false>(hB, wh + OFF_W3T, b3, hA,
                                 B_, 512, 1024, 1024, 1024, 512, 3);
        launch_gemm<64,64,false>(hA, wh + OFF_W4CT, bc, out + (size_t)t * C_,
                                 B_, C_, 512, 512, 512, LDO, 0);
    }

    if (out_size >= B_ * T_ * C_ + B_ * C_) {
        copy_init_tail_kernel<<<(B_ * C_ + 255) / 256, 256>>>(out);
    }
}

// round 6
// speedup vs baseline: 7.5924x; 1.2655x over previous
#include <cuda_runtime.h>
#include <cuda_fp16.h>
#include <cstdint>
#include <cstddef>

// Problem constants
#define B_  1024
#define T_  85
#define F_  36
#define H_  512
#define C_  69

#define ASTR 40        // halfs per smem row (32 data + 8 pad)
#define BK 32
#define STAGES 3

// ---------------------------------------------------------------------------
// Device globals
// ---------------------------------------------------------------------------
__device__ __half g_hA[B_ * 4 * H_];
__device__ __half g_hB[B_ * 4 * H_];
__device__ __half g_srch[B_ * 3072];           // fp16 source, padded rows
__device__ float  g_bc[2 * C_];                // composed biases
__device__ float  g_zeros[4 * H_];             // zero bias (never written)
__device__ float  g_P[(size_t)(T_ - 1) * B_ * 2048];  // precomputed layer-1 partial

// fp16 K-major weights [N][Kp], packed (offsets in halfs)
#define OFF_WI1T    0u          /* 2048 x 3072 */
#define OFF_WI2T    6291456u    /* 1024 x 2048 */
#define OFF_WI25CT  8388608u    /* 69   x 1024 */
#define OFF_W1ABT   8459264u    /* 2048 x 96   */
#define OFF_W1CT    8655872u    /* 2048 x 96   */
#define OFF_W12T    8852480u    /* 2048 x 2048 */
#define OFF_W2T     13046784u   /* 1024 x 2048 */
#define OFF_W22T    15143936u   /* 1024 x 1024 */
#define OFF_W3T     16192512u   /* 512  x 1024 */
#define OFF_W4CT    16716800u   /* 69   x 512  */
#define WH_TOTAL    16752128u
__device__ __half g_wh[WH_TOTAL];

// ---------------------------------------------------------------------------
__device__ __forceinline__ uint32_t smem_u32(const void* p) {
    return (uint32_t)__cvta_generic_to_shared(p);
}

__device__ __forceinline__ void mma_f16(float (&d)[4],
                                        const uint32_t (&a)[4],
                                        const uint32_t (&b)[2]) {
    asm volatile(
        "mma.sync.aligned.m16n8k16.row.col.f32.f16.f16.f32 "
        "{%0,%1,%2,%3}, {%4,%5,%6,%7}, {%8,%9}, {%0,%1,%2,%3};"
        : "+f"(d[0]), "+f"(d[1]), "+f"(d[2]), "+f"(d[3])
        : "r"(a[0]), "r"(a[1]), "r"(a[2]), "r"(a[3]),
          "r"(b[0]), "r"(b[1]));
}

__device__ __forceinline__ void ldsm_x4(uint32_t (&r)[4], uint32_t addr) {
    asm volatile(
        "ldmatrix.sync.aligned.m8n8.x4.shared.b16 {%0,%1,%2,%3}, [%4];"
        : "=r"(r[0]), "=r"(r[1]), "=r"(r[2]), "=r"(r[3]) : "r"(addr));
}

// ---------------------------------------------------------------------------
// FP16 GEMM: C[M,N] = act(A[M,K] @ Wt[N,Kp]^T + bias [+ addin])
// AMODE 0: A fp16 [M][lda], cp.async.  1: A fp32 [M][lda] strided, scalar.
//       2: A = srch base; row r -> (t=r>>10, b=r&1023), 72 contiguous halfs.
// flags: bit0 relu, bit1 fp16 out, bit2 add addin[row*addld+col].
// ---------------------------------------------------------------------------
template<int BM, int BN, int AMODE>
__global__ __launch_bounds__(256)
void gemm_f16_ldsm(const void* __restrict__ Aptr,
                   const __half* __restrict__ Wt,
                   const float* __restrict__ bias,
                   void* __restrict__ Cout,
                   int M, int N, int K, int Kp, int lda, int ldc, int flags,
                   const float* __restrict__ addin, int addld)
{
    constexpr int MT = BM / 32;
    constexpr int NT = BN / 32;

    extern __shared__ __align__(16) char smem_raw[];
    __half* Asm = (__half*)smem_raw;
    __half* Bsm = Asm + STAGES * BM * ASTR;

    const int bm   = blockIdx.y * BM;
    const int bn   = blockIdx.x * BN;
    const int tid  = threadIdx.x;
    const int lane = tid & 31;
    const int wid  = tid >> 5;
    const int warpM = wid >> 2;        // 0..1
    const int warpN = wid & 3;         // 0..3
    const int gp = lane >> 2;
    const int lq = lane & 3;

    const int KT = (K + BK - 1) / BK;

    auto fetchA = [&](int st, int kt) {
        if (AMODE == 0) {
            const __half* Ah = (const __half*)Aptr;
#pragma unroll
            for (int i = 0; i < BM * 4 / 256; i++) {
                int c   = i * 256 + tid;
                int row = c >> 2;
                int ch  = c & 3;
                int gk0 = kt * 32 + ch * 8;
                int rem = K - gk0;
                int bytes = rem >= 8 ? 16 : (rem > 0 ? rem * 2 : 0);
                const __half* g = Ah + (size_t)(bm + row) * lda + (gk0 < K ? gk0 : 0);
                uint32_t dst = smem_u32(Asm + (st * BM + row) * ASTR + ch * 8);
                asm volatile("cp.async.ca.shared.global [%0], [%1], 16, %2;"
                             :: "r"(dst), "l"(g), "r"(bytes));
            }
        } else if (AMODE == 1) {
            const float* Af = (const float*)Aptr;
#pragma unroll
            for (int i = 0; i < BM / 8; i++) {
                int e   = i * 256 + tid;
                int row = e >> 5;
                int kc  = e & 31;
                int gk  = kt * 32 + kc;
                float v = (gk < K) ? Af[(size_t)(bm + row) * lda + gk] : 0.f;
                Asm[(st * BM + row) * ASTR + kc] = __float2half(v);
            }
        } else {
            const __half* Sh = (const __half*)Aptr;
#pragma unroll
            for (int i = 0; i < BM / 8; i++) {
                int e   = i * 256 + tid;
                int row = e >> 5;
                int kc  = e & 31;
                int gk  = kt * 32 + kc;
                int gr  = bm + row;
                int tt  = gr >> 10;
                int b   = gr & 1023;
                __half v = __float2half(0.f);
                if (gk < 72) v = Sh[(size_t)b * 3072 + tt * 36 + gk];
                Asm[(st * BM + row) * ASTR + kc] = v;
            }
        }
    };

    auto fetchB = [&](int st, int kt) {
#pragma unroll
        for (int i = 0; i < BN * 4 / 256; i++) {
            int c   = i * 256 + tid;
            int row = c >> 2;
            int ch  = c & 3;
            int gn  = bn + row;
            int bytes = (gn < N) ? 16 : 0;
            const __half* g = Wt + (size_t)(gn < N ? gn : 0) * Kp + kt * 32 + ch * 8;
            uint32_t dst = smem_u32(Bsm + (st * BN + row) * ASTR + ch * 8);
            asm volatile("cp.async.ca.shared.global [%0], [%1], 16, %2;"
                         :: "r"(dst), "l"(g), "r"(bytes));
        }
    };

    float acc[MT][NT][4];
#pragma unroll
    for (int i = 0; i < MT; i++)
#pragma unroll
        for (int j = 0; j < NT; j++)
#pragma unroll
            for (int v = 0; v < 4; v++) acc[i][j][v] = 0.f;

    // prologue: 2 stages ahead
#pragma unroll
    for (int s = 0; s < STAGES - 1; s++) {
        if (s < KT) { fetchA(s, s); fetchB(s, s); }
        asm volatile("cp.async.commit_group;" ::: "memory");
    }

    const int aRowSel = lane & 15;
    const int aColSel = (lane >> 4) << 3;
    const int bRowSel = ((lane >> 4) << 3) + (lane & 7);
    const int bColSel = ((lane >> 3) & 1) << 3;

    for (int kt = 0; kt < KT; kt++) {
        asm volatile("cp.async.wait_group 1;" ::: "memory");
        __syncthreads();

        const int nf = kt + 2;
        if (nf < KT) { fetchA(nf % STAGES, nf); fetchB(nf % STAGES, nf); }
        asm volatile("cp.async.commit_group;" ::: "memory");

        const int st = kt % STAGES;
#pragma unroll
        for (int kk = 0; kk < BK; kk += 16) {
            uint32_t af[MT][4];
#pragma unroll
            for (int mt = 0; mt < MT; mt++) {
                int r0 = warpM * (BM / 2) + mt * 16 + aRowSel;
                ldsm_x4(af[mt], smem_u32(Asm + (st * BM + r0) * ASTR + kk + aColSel));
            }
            uint32_t bf[NT][2];
#pragma unroll
            for (int p = 0; p < NT / 2; p++) {
                int c0 = warpN * (BN / 4) + p * 16 + bRowSel;
                uint32_t r4[4];
                ldsm_x4(r4, smem_u32(Bsm + (st * BN + c0) * ASTR + kk + bColSel));
                bf[2 * p][0]     = r4[0];
                bf[2 * p][1]     = r4[1];
                bf[2 * p + 1][0] = r4[2];
                bf[2 * p + 1][1] = r4[3];
            }
#pragma unroll
            for (int mt = 0; mt < MT; mt++)
#pragma unroll
                for (int nt = 0; nt < NT; nt++)
                    mma_f16(acc[mt][nt], af[mt], bf[nt]);
        }
    }

    // ---- epilogue ----
    const bool relu = flags & 1;
    const bool houT = flags & 2;
    const bool padd = flags & 4;
#pragma unroll
    for (int mt = 0; mt < MT; mt++) {
#pragma unroll
        for (int nt = 0; nt < NT; nt++) {
            int row0 = bm + warpM * (BM / 2) + mt * 16 + gp;
            int col0 = bn + warpN * (BN / 4) + nt * 8 + lq * 2;
            float b0 = (col0 < N)     ? bias[col0]     : 0.f;
            float b1 = (col0 + 1 < N) ? bias[col0 + 1] : 0.f;
            float x0 = acc[mt][nt][0] + b0;
            float x1 = acc[mt][nt][1] + b1;
            float x2 = acc[mt][nt][2] + b0;
            float x3 = acc[mt][nt][3] + b1;
            if (padd) {
                const float* p0 = addin + (size_t)row0 * addld + col0;
                const float* p8 = addin + (size_t)(row0 + 8) * addld + col0;
                x0 += p0[0]; x1 += p0[1];
                x2 += p8[0]; x3 += p8[1];
            }
            if (relu) {
                x0 = fmaxf(x0, 0.f); x1 = fmaxf(x1, 0.f);
                x2 = fmaxf(x2, 0.f); x3 = fmaxf(x3, 0.f);
            }
            if (houT) {
                __half* cp = (__half*)Cout;
                *(__half2*)(cp + (size_t)row0 * ldc + col0) = __floats2half2_rn(x0, x1);
                *(__half2*)(cp + (size_t)(row0 + 8) * ldc + col0) = __floats2half2_rn(x2, x3);
            } else {
                float* cp = (float*)Cout;
                if (col0 < N) {
                    cp[(size_t)row0 * ldc + col0] = x0;
                    cp[(size_t)(row0 + 8) * ldc + col0] = x2;
                }
                if (col0 + 1 < N) {
                    cp[(size_t)row0 * ldc + col0 + 1] = x1;
                    cp[(size_t)(row0 + 8) * ldc + col0 + 1] = x3;
                }
            }
        }
    }
}

// ---------------------------------------------------------------------------
// Prep kernels
// ---------------------------------------------------------------------------
__global__ void src_round_kernel(const float* __restrict__ src,
                                 __half* __restrict__ dst)
{
    int i = blockIdx.x * blockDim.x + threadIdx.x;
    if (i >= B_ * 3072) return;
    int b = i / 3072;
    int j = i - b * 3072;
    float v = (j < T_ * F_) ? src[(size_t)b * T_ * F_ + j] : 0.f;
    dst[i] = __float2half(v);
}

__global__ void transpose_h_kernel(const float* __restrict__ W,
                                   __half* __restrict__ Wt,
                                   int K, int N, int Kp, int ldw)
{
    __shared__ float tile[32][33];
    int k0 = blockIdx.x * 32;
    int n0 = blockIdx.y * 32;
    int tx = threadIdx.x, ty = threadIdx.y;
    for (int i = ty; i < 32; i += 8) {
        int k = k0 + i, n = n0 + tx;
        tile[i][tx] = (k < K && n < N) ? W[(size_t)k * ldw + n] : 0.f;
    }
    __syncthreads();
    for (int i = ty; i < 32; i += 8) {
        int n = n0 + i, k = k0 + tx;
        if (n < N && k < Kp)
            Wt[(size_t)n * Kp + k] = __float2half(tile[tx][i]);
    }
}

__global__ void compose_w_kernel(const float* __restrict__ W1,
                                 const float* __restrict__ W2,
                                 __half* __restrict__ outT,
                                 int D, int I, int N)
{
    __shared__ float row[512];
    int d = blockIdx.x;
    for (int i = threadIdx.x; i < I; i += 128) row[i] = W1[(size_t)d * I + i];
    __syncthreads();
    for (int n = threadIdx.x; n < N; n += 128) {
        float s = 0.f;
        for (int i = 0; i < I; i++) s += row[i] * W2[(size_t)i * N + n];
        outT[(size_t)n * D + d] = __float2half(s);
    }
}

__global__ void compose_bias_kernel(const float* __restrict__ b1,
                                    const float* __restrict__ W2,
                                    const float* __restrict__ b2,
                                    float* __restrict__ bc, int I, int N)
{
    int n = threadIdx.x;
    if (n >= N) return;
    float s = b2[n];
    for (int i = 0; i < I; i++) s += b1[i] * W2[(size_t)i * N + n];
    bc[n] = s;
}

__global__ void copy_init_tail_kernel(float* __restrict__ out)
{
    int i = blockIdx.x * blockDim.x + threadIdx.x;
    if (i >= B_ * C_) return;
    int b = i / C_;
    int c = i - b * C_;
    out[(size_t)B_ * T_ * C_ + i] = out[(size_t)b * T_ * C_ + c];
}

// ---------------------------------------------------------------------------
template<int BM, int BN, int AMODE>
static void launch_gemm(const void* A, const __half* Wt, const float* bias,
                        void* C, int M, int N, int K, int Kp, int lda, int ldc,
                        int flags, const float* addin = nullptr, int addld = 0)
{
    const int sbytes = STAGES * (BM + BN) * ASTR * 2;
    cudaFuncSetAttribute(gemm_f16_ldsm<BM, BN, AMODE>,
                         cudaFuncAttributeMaxDynamicSharedMemorySize, sbytes);
    dim3 grid((N + BN - 1) / BN, M / BM);
    gemm_f16_ldsm<BM, BN, AMODE><<<grid, 256, sbytes>>>(
        A, Wt, bias, C, M, N, K, Kp, lda, ldc, flags, addin, addld);
}

static void trsp(const float* W, __half* Wt, int K, int N, int Kp, int ldw)
{
    dim3 grid((Kp + 31) / 32, (N + 31) / 32);
    transpose_h_kernel<<<grid, dim3(32, 8)>>>(W, Wt, K, N, Kp, ldw);
}

extern "C" void kernel_launch(void* const* d_in, const int* in_sizes, int n_in,
                              void* d_out, int out_size)
{
    const float* src  = (const float*)d_in[0];
    const float* wi1  = (const float*)d_in[1];
    const float* bi1  = (const float*)d_in[2];
    const float* wi2  = (const float*)d_in[3];
    const float* bi2  = (const float*)d_in[4];
    const float* wi25 = (const float*)d_in[5];
    const float* bi25 = (const float*)d_in[6];
    const float* wi3  = (const float*)d_in[7];
    const float* bi3  = (const float*)d_in[8];
    const float* w1   = (const float*)d_in[9];
    const float* b1   = (const float*)d_in[10];
    const float* w12  = (const float*)d_in[11];
    const float* b12  = (const float*)d_in[12];
    const float* w2   = (const float*)d_in[13];
    const float* b2   = (const float*)d_in[14];
    const float* w22  = (const float*)d_in[15];
    const float* b22  = (const float*)d_in[16];
    const float* w3   = (const float*)d_in[17];
    const float* b3   = (const float*)d_in[18];
    const float* w4   = (const float*)d_in[19];
    const float* b4   = (const float*)d_in[20];
    const float* w4d  = (const float*)d_in[21];
    const float* b4d  = (const float*)d_in[22];

    float* out = (float*)d_out;

    __half *hA, *hB, *srch, *wh;
    float *bc, *zeros, *P;
    cudaGetSymbolAddress((void**)&hA,    g_hA);
    cudaGetSymbolAddress((void**)&hB,    g_hB);
    cudaGetSymbolAddress((void**)&srch,  g_srch);
    cudaGetSymbolAddress((void**)&wh,    g_wh);
    cudaGetSymbolAddress((void**)&bc,    g_bc);
    cudaGetSymbolAddress((void**)&zeros, g_zeros);
    cudaGetSymbolAddress((void**)&P,     g_P);

    // ---- prep ----
    trsp(wi1, wh + OFF_WI1T, 3060, 2048, 3072, 2048);
    trsp(wi2, wh + OFF_WI2T, 2048, 1024, 2048, 1024);
    trsp(w1,               wh + OFF_W1ABT, 72, 2048, 96, 2048);   // rows 0..71
    trsp(w1 + 72 * 2048,   wh + OFF_W1CT,  69, 2048, 96, 2048);   // rows 72..140
    trsp(w12, wh + OFF_W12T, 2048, 2048, 2048, 2048);
    trsp(w2,  wh + OFF_W2T,  2048, 1024, 2048, 1024);
    trsp(w22, wh + OFF_W22T, 1024, 1024, 1024, 1024);
    trsp(w3,  wh + OFF_W3T,  1024, 512,  1024, 512);
    compose_w_kernel<<<1024, 128>>>(wi25, wi3, wh + OFF_WI25CT, 1024, 512, C_);
    compose_w_kernel<<<512,  128>>>(w4,   w4d, wh + OFF_W4CT,   512,  512, C_);
    compose_bias_kernel<<<1, 128>>>(b4,   w4d, b4d, bc,      512, C_);
    compose_bias_kernel<<<1, 128>>>(bi25, wi3, bi3, bc + C_, 512, C_);
    src_round_kernel<<<(B_ * 3072 + 511) / 512, 512>>>(src, srch);

    const int LDO = T_ * C_;

    // ---- P = concat(src[t-1], src[t]) @ W1ab + b1, all 84 steps in one GEMM
    launch_gemm<128, 128, 2>(srch, wh + OFF_W1ABT, b1, P,
                             (T_ - 1) * B_, 2048, 72, 96, 0, 2048, 0);

    // ---- getInitialPos: 3060 -> 2048 -> 1024 -> 69 (wi25∘wi3 composed)
    launch_gemm<128, 128, 0>(srch, wh + OFF_WI1T, bi1, hA,
                             B_, 2048, 3060, 3072, 3072, 2048, 3);
    launch_gemm<64, 128, 0>(hA, wh + OFF_WI2T, bi2, hB,
                            B_, 1024, 2048, 2048, 2048, 1024, 3);
    launch_gemm<64, 64, 0>(hB, wh + OFF_WI25CT, bc + C_, out,
                           B_, C_, 1024, 1024, 1024, LDO, 0);

    // ---- scan: 84 steps x 6 GEMMs
    for (int t = 1; t < T_; t++) {
        // layer 1: prev_out @ W1c + P[t-1], relu, fp16 out
        launch_gemm<128, 128, 1>(out + (size_t)(t - 1) * C_, wh + OFF_W1CT, zeros, hA,
                                 B_, 2048, C_, 96, LDO, 2048, 7,
                                 P + (size_t)(t - 1) * B_ * 2048, 2048);
        launch_gemm<128, 128, 0>(hA, wh + OFF_W12T, b12, hB,
                                 B_, 2048, 2048, 2048, 2048, 2048, 3);
        launch_gemm<64, 128, 0>(hB, wh + OFF_W2T, b2, hA,
                                B_, 1024, 2048, 2048, 2048, 1024, 3);
        launch_gemm<64, 128, 0>(hA, wh + OFF_W22T, b22, hB,
                                B_, 1024, 1024, 1024, 1024, 1024, 3);
        launch_gemm<64, 64, 0>(hB, wh + OFF_W3T, b3, hA,
                               B_, 512, 1024, 1024, 1024, 512, 3);
        launch_gemm<64, 64, 0>(hA, wh + OFF_W4CT, bc, out + (size_t)t * C_,
                               B_, C_, 512, 512, 512, LDO, 0);
    }

    if (out_size >= B_ * T_ * C_ + B_ * C_) {
        copy_init_tail_kernel<<<(B_ * C_ + 255) / 256, 256>>>(out);
    }
}